// round 9
// baseline (speedup 1.0000x reference)
#include <cuda_runtime.h>

#define HH 128
#define WW 128
#define CC 16
#define FF 16
#define CF (CC * FF)
#define NB 2
#define SNX 32
#define SNY 32
#define NG 33            // aligned 4x4 groups: start = 4g-2, g = 0..32

// Group sums: G = sum b over 4x4 group, P = sum pet*b. 1.1 MB each.
__device__ float g_G[(size_t)NB * NG * NG * CF];
__device__ float g_P[(size_t)NB * NG * NG * CF];

// ---------------------------------------------------------------------------
// K1: group sums. CTA = (quarter q, gx, b). Quarter q covers gy = 8q..8q+7
// (q=3: 24..32, 9 groups). Each b pixel read exactly once, fully coalesced.
// ---------------------------------------------------------------------------
__global__ __launch_bounds__(256) void groupsum_kernel(
    const float* __restrict__ pet, const float* __restrict__ bfeat)
{
    __shared__ float pet_s[4 * 36 * CC];   // up to 9.2 KB

    const int q  = blockIdx.x;             // 0..3
    const int gx = blockIdx.y;             // 0..32
    const int bz = blockIdx.z;
    const int t  = threadIdx.x;
    const int c  = t >> 4;

    const int ngy   = (q == 3) ? 9 : 8;
    const int gy0   = q * 8;
    const int c0    = 4 * gy0 - 2;
    const int ncols = 4 * ngy;             // 32 or 36
    const int r0    = 4 * gx - 2;

    // stage pet for the 4 x ncols strip (zero outside image)
    for (int idx = t; idx < 4 * ncols * CC; idx += 256) {
        int cc = idx & 15, pix = idx >> 4;
        int u = pix / ncols, v = pix - u * ncols;
        int r = r0 + u, col = c0 + v;
        float val = 0.f;
        if ((unsigned)r < HH && (unsigned)col < WW)
            val = pet[((bz * HH + r) * WW + col) * CC + cc];
        pet_s[idx] = val;
    }
    __syncthreads();

    const float* bb = bfeat + (size_t)bz * HH * WW * CF + t;

    for (int g = 0; g < ngy; g++) {
        float d = 0.f, p = 0.f;
#pragma unroll
        for (int u = 0; u < 4; u++) {
            int r = r0 + u;
            if ((unsigned)r >= HH) continue;
#pragma unroll
            for (int v = 0; v < 4; v++) {
                int col = c0 + 4 * g + v;
                if ((unsigned)col >= WW) continue;
                float bv = __ldg(bb + (r * WW + col) * CF);
                float pv = pet_s[(u * ncols + 4 * g + v) * CC + c];
                d += bv;
                p = fmaf(pv, bv, p);
            }
        }
        size_t o = (((size_t)bz * NG + gx) * NG + (gy0 + g)) * CF + t;
        g_G[o] = d;
        g_P[o] = p;
    }
}

// ---------------------------------------------------------------------------
// K2: out(x,y,c) = 0.25 * sum_f b * S.  S built from G/P on the fly:
// window (snx,sny) = 2x2 sum of groups (snx..snx+1, sny..sny+1);
// ratio = divide_no_nan(P2, G2); S = sum of <=4 covering windows' ratios.
// b loads issued first so DRAM latency overlaps the S computation.
// ---------------------------------------------------------------------------
__global__ __launch_bounds__(256) void apply_kernel(
    const float* __restrict__ bfeat, float* __restrict__ out)
{
    __shared__ float S2[2][CF];   // natural layout [c*16 + f]

    const int A2 = blockIdx.x;   // 0..16 (y-block pair)
    const int a  = blockIdx.y;   // 0..32 (x-block)
    const int bz = blockIdx.z;
    const int t  = threadIdx.x;

    const int qq = t & 63;       // float4 slot within pixel
    const int pg = t >> 6;       // x-row within tile
    const int c  = qq >> 2;
    const int f4 = qq & 3;

    const int x = 4 * a - 2 + pg;
    const bool okx = (unsigned)x < HH;
    const float* rowbase = bfeat + ((size_t)(bz * HH + x) * WW) * CF + qq * 4;

    // ---- issue all 8 independent b loads first ----
    float4 bv[8];
#pragma unroll
    for (int m = 0; m < 8; m++) {
        int y = 8 * A2 - 2 + m;
        bv[m] = make_float4(0.f, 0.f, 0.f, 0.f);
        if (okx && (unsigned)y < WW)
            bv[m] = __ldg((const float4*)(rowbase + (size_t)y * CF));
    }

    // ---- load G/P neighborhood: gx = a-1..a+1, gy = 2A2-1..2A2+2 ----
    float Gv[3][4], Pv[3][4];
#pragma unroll
    for (int i = 0; i < 3; i++) {
        int gx = a - 1 + i;
#pragma unroll
        for (int j = 0; j < 4; j++) {
            int gy = 2 * A2 - 1 + j;
            bool ok = ((unsigned)gx < NG) && ((unsigned)gy < NG);
            size_t o = (((size_t)bz * NG + gx) * NG + gy) * CF + t;
            Gv[i][j] = ok ? __ldg(&g_G[o]) : 0.f;
            Pv[i][j] = ok ? __ldg(&g_P[o]) : 0.f;
        }
    }

    // ---- S for the two y-blocks ----
#pragma unroll
    for (int s = 0; s < 2; s++) {
        int blk = 2 * A2 + s;
        float acc = 0.f;
#pragma unroll
        for (int da = 0; da < 2; da++) {
            int snx = a - 1 + da;
            if ((unsigned)snx >= SNX) continue;
#pragma unroll
            for (int db = 0; db < 2; db++) {
                int sny = blk - 1 + db;
                if ((unsigned)sny >= SNY) continue;
                int j0 = s + db;          // gy offset of window start
                float g2 = Gv[da][j0] + Gv[da][j0 + 1]
                         + Gv[da + 1][j0] + Gv[da + 1][j0 + 1];
                float p2 = Pv[da][j0] + Pv[da][j0 + 1]
                         + Pv[da + 1][j0] + Pv[da + 1][j0 + 1];
                acc += (g2 != 0.f) ? (p2 / g2) : 0.f;   // divide_no_nan
            }
        }
        S2[s][t] = acc;
    }
    __syncthreads();

    const bool lead = ((qq & 3) == 0);
#pragma unroll
    for (int m = 0; m < 8; m++) {
        int y = 8 * A2 - 2 + m;
        const int s = m >> 2;
        const float4 sv = *(const float4*)(&S2[s][c * 16 + f4 * 4]);
        float dot = bv[m].x * sv.x + bv[m].y * sv.y + bv[m].z * sv.z + bv[m].w * sv.w;
        dot += __shfl_xor_sync(0xffffffffu, dot, 1);
        dot += __shfl_xor_sync(0xffffffffu, dot, 2);
        if (lead && okx && (unsigned)y < WW)
            out[((bz * HH + x) * WW + y) * CC + c] = 0.25f * dot;
    }
}

extern "C" void kernel_launch(void* const* d_in, const int* in_sizes, int n_in,
                              void* d_out, int out_size)
{
    // Input order per reference signature: mr (unused), pet, b, px, py, sx, sy
    const float* pet   = (const float*)d_in[1];
    const float* bfeat = (const float*)d_in[2];

    dim3 grid1(4, NG, NB);                   // quarters x gx x batch = 264 CTAs
    groupsum_kernel<<<grid1, 256>>>(pet, bfeat);

    dim3 grid2(17, 33, NB);                  // y-pairs x x-blocks
    apply_kernel<<<grid2, 256>>>(bfeat, (float*)d_out);
}

// round 10
// speedup vs baseline: 1.0898x; 1.0898x over previous
#include <cuda_runtime.h>

#define HH 128
#define WW 128
#define CC 16
#define FF 16
#define CF (CC * FF)
#define NB 2
#define SNX 32
#define SNY 32
#define NG 33            // aligned 4x4 groups: start = 4g-2, g = 0..32
#define QYB 11           // y-blocks per apply CTA (3*11 = 33)

// Group sums: G = sum b over 4x4 group, P = sum pet*b. 1.1 MB each.
__device__ float g_G[(size_t)NB * NG * NG * CF];
__device__ float g_P[(size_t)NB * NG * NG * CF];

// ---------------------------------------------------------------------------
// K1: group sums, double-buffered prefetch over groups.
// CTA = (quarter q, gx, b). Each b pixel read exactly once, coalesced.
// ---------------------------------------------------------------------------
__global__ __launch_bounds__(256) void groupsum_kernel(
    const float* __restrict__ pet, const float* __restrict__ bfeat)
{
    __shared__ float pet_s[4 * 36 * CC];   // 9.2 KB

    const int q  = blockIdx.x;             // 0..3
    const int gx = blockIdx.y;             // 0..32
    const int bz = blockIdx.z;
    const int t  = threadIdx.x;
    const int c  = t >> 4;

    const int ngy   = (q == 3) ? 9 : 8;
    const int gy0   = q * 8;
    const int c0    = 4 * gy0 - 2;
    const int ncols = 4 * ngy;
    const int r0    = 4 * gx - 2;

    for (int idx = t; idx < 4 * ncols * CC; idx += 256) {
        int cc = idx & 15, pix = idx >> 4;
        int u = pix / ncols, v = pix - u * ncols;
        int r = r0 + u, col = c0 + v;
        float val = 0.f;
        if ((unsigned)r < HH && (unsigned)col < WW)
            val = pet[((bz * HH + r) * WW + col) * CC + cc];
        pet_s[idx] = val;
    }
    __syncthreads();

    const float* bb = bfeat + (size_t)bz * HH * WW * CF + t;

    float buf[2][16];
    auto load_group = [&](int g, float* dst) {
#pragma unroll
        for (int u = 0; u < 4; u++) {
            int r = r0 + u;
            bool rowok = (unsigned)r < HH;
#pragma unroll
            for (int v = 0; v < 4; v++) {
                int col = c0 + 4 * g + v;
                float x = 0.f;
                if (rowok && (unsigned)col < WW)
                    x = __ldg(bb + (r * WW + col) * CF);
                dst[u * 4 + v] = x;
            }
        }
    };

    load_group(0, buf[0]);
#pragma unroll
    for (int g = 0; g < 9; g++) {
        if (g >= ngy) continue;
        if (g + 1 < ngy) load_group(g + 1, buf[(g + 1) & 1]);
        const float* B = buf[g & 1];
        float d = 0.f, p = 0.f;
#pragma unroll
        for (int u = 0; u < 4; u++)
#pragma unroll
            for (int v = 0; v < 4; v++) {
                float bv = B[u * 4 + v];
                float pv = pet_s[(u * ncols + 4 * g + v) * CC + c];
                d += bv;
                p = fmaf(pv, bv, p);
            }
        size_t o = (((size_t)bz * NG + gx) * NG + (gy0 + g)) * CF + t;
        g_G[o] = d;
        g_P[o] = p;
    }
}

// ---------------------------------------------------------------------------
// K2: out(x,y,c) = 0.25 * sum_f b * S.
// CTA = 4 x-rows x 11 y-blocks (44 y). b loads pipelined at distance 2 blocks;
// S built by streaming G/P rows with running x-pair sums.
// ---------------------------------------------------------------------------
__global__ __launch_bounds__(256) void apply_kernel(
    const float* __restrict__ bfeat, float* __restrict__ out)
{
    __shared__ float Ssm[QYB][CF];

    const int qy = blockIdx.x;   // 0..2
    const int a  = blockIdx.y;   // 0..32
    const int bz = blockIdx.z;
    const int t  = threadIdx.x;

    const int qq = t & 63;
    const int pg = t >> 6;
    const int c  = qq >> 2;
    const int f4 = qq & 3;

    const int x = 4 * a - 2 + pg;
    const bool okx = (unsigned)x < HH;
    const float* rowbase = bfeat + ((size_t)(bz * HH + x) * WW) * CF + qq * 4;
    const int blk0 = QYB * qy;

    float4 bbuf[3][4];
    auto load_blk = [&](int s, float4* dst) {
        int blk = blk0 + s;
#pragma unroll
        for (int jj = 0; jj < 4; jj++) {
            int y = 4 * blk - 2 + jj;
            float4 v = make_float4(0.f, 0.f, 0.f, 0.f);
            if (okx && (unsigned)y < WW)
                v = __ldg((const float4*)(rowbase + (size_t)y * CF));
            dst[jj] = v;
        }
    };

    // prime the b pipeline before touching G/P
    load_blk(0, bbuf[0]);
    load_blk(1, bbuf[1]);

    // ---- stream G/P rows gy = blk0-1 .. blk0+11, build S[0..10] ----
    {
        float S[QYB];
#pragma unroll
        for (int s = 0; s < QYB; s++) S[s] = 0.f;

        float xg0p = 0.f, xg1p = 0.f, xp0p = 0.f, xp1p = 0.f;
#pragma unroll
        for (int w = 0; w <= 12; w++) {
            int gy = blk0 - 1 + w;
            float G0 = 0.f, G1 = 0.f, G2v = 0.f;
            float P0 = 0.f, P1 = 0.f, P2v = 0.f;
            if ((unsigned)gy < NG) {
#pragma unroll
                for (int i = 0; i < 3; i++) {
                    int gxx = a - 1 + i;
                    if ((unsigned)gxx >= NG) continue;
                    size_t o = (((size_t)bz * NG + gxx) * NG + gy) * CF + t;
                    float gv = __ldg(&g_G[o]);
                    float pv = __ldg(&g_P[o]);
                    if (i == 0) { G0 = gv; P0 = pv; }
                    else if (i == 1) { G1 = gv; P1 = pv; }
                    else { G2v = gv; P2v = pv; }
                }
            }
            float xg0 = G0 + G1, xg1 = G1 + G2v;
            float xp0 = P0 + P1, xp1 = P1 + P2v;
            if (w >= 1) {
                int sny = blk0 - 2 + w;          // window row index
                float rsum = 0.f;
                if ((unsigned)sny < SNY) {
                    float g20 = xg0p + xg0, p20 = xp0p + xp0;
                    float g21 = xg1p + xg1, p21 = xp1p + xp1;
                    if ((unsigned)(a - 1) < SNX && g20 != 0.f) rsum += p20 / g20;
                    if ((unsigned)a < SNX       && g21 != 0.f) rsum += p21 / g21;
                }
                int wp = w - 1;                  // 0..11
                if (wp <= QYB - 1) S[wp] += rsum;
                if (wp - 1 >= 0)   S[wp - 1] += rsum;
            }
            xg0p = xg0; xg1p = xg1; xp0p = xp0; xp1p = xp1;
        }
#pragma unroll
        for (int s = 0; s < QYB; s++) Ssm[s][t] = S[s];
    }
    __syncthreads();

    // ---- pipelined apply over 11 y-blocks ----
    const bool lead = ((qq & 3) == 0);
#pragma unroll
    for (int s = 0; s < QYB; s++) {
        if (s + 2 < QYB) load_blk(s + 2, bbuf[(s + 2) % 3]);
        const float4* B = bbuf[s % 3];
        const float4 sv = *(const float4*)(&Ssm[s][c * 16 + f4 * 4]);
#pragma unroll
        for (int jj = 0; jj < 4; jj++) {
            float dot = B[jj].x * sv.x + B[jj].y * sv.y
                      + B[jj].z * sv.z + B[jj].w * sv.w;
            dot += __shfl_xor_sync(0xffffffffu, dot, 1);
            dot += __shfl_xor_sync(0xffffffffu, dot, 2);
            int y = 4 * (blk0 + s) - 2 + jj;
            if (lead && okx && (unsigned)y < WW)
                out[((bz * HH + x) * WW + y) * CC + c] = 0.25f * dot;
        }
    }
}

extern "C" void kernel_launch(void* const* d_in, const int* in_sizes, int n_in,
                              void* d_out, int out_size)
{
    // Input order per reference signature: mr (unused), pet, b, px, py, sx, sy
    const float* pet   = (const float*)d_in[1];
    const float* bfeat = (const float*)d_in[2];

    dim3 grid1(4, NG, NB);                   // 264 CTAs
    groupsum_kernel<<<grid1, 256>>>(pet, bfeat);

    dim3 grid2(3, NG, NB);                   // 198 CTAs
    apply_kernel<<<grid2, 256>>>(bfeat, (float*)d_out);
}

// round 11
// speedup vs baseline: 1.2309x; 1.1295x over previous
#include <cuda_runtime.h>

#define HH 128
#define WW 128
#define CC 16
#define FF 16
#define CF (CC * FF)
#define NB 2
#define SNX 32
#define SNY 32
#define NG 33            // aligned 4x4 groups: start = 4g-2, g = 0..32

// Group sums: G = sum b over 4x4 group, P = sum pet*b. 1.1 MB each.
__device__ float g_G[(size_t)NB * NG * NG * CF];
__device__ float g_P[(size_t)NB * NG * NG * CF];

// ---------------------------------------------------------------------------
// K1: group sums, double-buffered prefetch over groups (R10 version, ~4.4us).
// CTA = (quarter q, gx, b). Each b pixel read exactly once, coalesced.
// ---------------------------------------------------------------------------
__global__ __launch_bounds__(256) void groupsum_kernel(
    const float* __restrict__ pet, const float* __restrict__ bfeat)
{
    __shared__ float pet_s[4 * 36 * CC];   // 9.2 KB

    const int q  = blockIdx.x;             // 0..3
    const int gx = blockIdx.y;             // 0..32
    const int bz = blockIdx.z;
    const int t  = threadIdx.x;
    const int c  = t >> 4;

    const int ngy   = (q == 3) ? 9 : 8;
    const int gy0   = q * 8;
    const int c0    = 4 * gy0 - 2;
    const int ncols = 4 * ngy;
    const int r0    = 4 * gx - 2;

    for (int idx = t; idx < 4 * ncols * CC; idx += 256) {
        int cc = idx & 15, pix = idx >> 4;
        int u = pix / ncols, v = pix - u * ncols;
        int r = r0 + u, col = c0 + v;
        float val = 0.f;
        if ((unsigned)r < HH && (unsigned)col < WW)
            val = pet[((bz * HH + r) * WW + col) * CC + cc];
        pet_s[idx] = val;
    }
    __syncthreads();

    const float* bb = bfeat + (size_t)bz * HH * WW * CF + t;

    float buf[2][16];
    auto load_group = [&](int g, float* dst) {
#pragma unroll
        for (int u = 0; u < 4; u++) {
            int r = r0 + u;
            bool rowok = (unsigned)r < HH;
#pragma unroll
            for (int v = 0; v < 4; v++) {
                int col = c0 + 4 * g + v;
                float x = 0.f;
                if (rowok && (unsigned)col < WW)
                    x = __ldg(bb + (r * WW + col) * CF);
                dst[u * 4 + v] = x;
            }
        }
    };

    load_group(0, buf[0]);
#pragma unroll
    for (int g = 0; g < 9; g++) {
        if (g >= ngy) continue;
        if (g + 1 < ngy) load_group(g + 1, buf[(g + 1) & 1]);
        const float* B = buf[g & 1];
        float d = 0.f, p = 0.f;
#pragma unroll
        for (int u = 0; u < 4; u++)
#pragma unroll
            for (int v = 0; v < 4; v++) {
                float bv = B[u * 4 + v];
                float pv = pet_s[(u * ncols + 4 * g + v) * CC + c];
                d += bv;
                p = fmaf(pv, bv, p);
            }
        size_t o = (((size_t)bz * NG + gx) * NG + (gy0 + g)) * CF + t;
        g_G[o] = d;
        g_P[o] = p;
    }
}

// ---------------------------------------------------------------------------
// K2: out(x,y,c) = 0.25 * sum_f b * S (R9 wide-grid version, G/P x-pair-folded).
// CTA = 4x8 output tile, grid 1122. b loads issued first.
// ---------------------------------------------------------------------------
__global__ __launch_bounds__(256) void apply_kernel(
    const float* __restrict__ bfeat, float* __restrict__ out)
{
    __shared__ float S2[2][CF];   // natural layout [c*16 + f]

    const int A2 = blockIdx.x;   // 0..16 (y-block pair)
    const int a  = blockIdx.y;   // 0..32 (x-block)
    const int bz = blockIdx.z;
    const int t  = threadIdx.x;

    const int qq = t & 63;
    const int pg = t >> 6;
    const int c  = qq >> 2;
    const int f4 = qq & 3;

    const int x = 4 * a - 2 + pg;
    const bool okx = (unsigned)x < HH;
    const float* rowbase = bfeat + ((size_t)(bz * HH + x) * WW) * CF + qq * 4;

    // ---- issue all 8 independent b loads first ----
    float4 bv[8];
#pragma unroll
    for (int m = 0; m < 8; m++) {
        int y = 8 * A2 - 2 + m;
        bv[m] = make_float4(0.f, 0.f, 0.f, 0.f);
        if (okx && (unsigned)y < WW)
            bv[m] = __ldg((const float4*)(rowbase + (size_t)y * CF));
    }

    // ---- load G/P neighborhood folded into x-pair sums ----
    // xg[da][j] = G[a-1+da][gy] + G[a+da][gy], j over gy = 2A2-1..2A2+2
    float xg[2][4], xp[2][4];
#pragma unroll
    for (int j = 0; j < 4; j++) {
        int gy = 2 * A2 - 1 + j;
        float g0 = 0.f, g1 = 0.f, g2v = 0.f;
        float p0 = 0.f, p1 = 0.f, p2v = 0.f;
        if ((unsigned)gy < NG) {
#pragma unroll
            for (int i = 0; i < 3; i++) {
                int gxx = a - 1 + i;
                if ((unsigned)gxx >= NG) continue;
                size_t o = (((size_t)bz * NG + gxx) * NG + gy) * CF + t;
                float gv = __ldg(&g_G[o]);
                float pv = __ldg(&g_P[o]);
                if (i == 0)      { g0 = gv; p0 = pv; }
                else if (i == 1) { g1 = gv; p1 = pv; }
                else             { g2v = gv; p2v = pv; }
            }
        }
        xg[0][j] = g0 + g1;  xg[1][j] = g1 + g2v;
        xp[0][j] = p0 + p1;  xp[1][j] = p1 + p2v;
    }

    // ---- S for the two y-blocks ----
#pragma unroll
    for (int s = 0; s < 2; s++) {
        int blk = 2 * A2 + s;
        float acc = 0.f;
#pragma unroll
        for (int da = 0; da < 2; da++) {
            int snx = a - 1 + da;
            if ((unsigned)snx >= SNX) continue;
#pragma unroll
            for (int db = 0; db < 2; db++) {
                int sny = blk - 1 + db;
                if ((unsigned)sny >= SNY) continue;
                int j0 = s + db;
                float g2 = xg[da][j0] + xg[da][j0 + 1];
                float p2 = xp[da][j0] + xp[da][j0 + 1];
                acc += (g2 != 0.f) ? (p2 / g2) : 0.f;   // divide_no_nan
            }
        }
        S2[s][t] = acc;
    }
    __syncthreads();

    const bool lead = ((qq & 3) == 0);
#pragma unroll
    for (int m = 0; m < 8; m++) {
        int y = 8 * A2 - 2 + m;
        const int s = m >> 2;
        const float4 sv = *(const float4*)(&S2[s][c * 16 + f4 * 4]);
        float dot = bv[m].x * sv.x + bv[m].y * sv.y + bv[m].z * sv.z + bv[m].w * sv.w;
        dot += __shfl_xor_sync(0xffffffffu, dot, 1);
        dot += __shfl_xor_sync(0xffffffffu, dot, 2);
        if (lead && okx && (unsigned)y < WW)
            out[((bz * HH + x) * WW + y) * CC + c] = 0.25f * dot;
    }
}

extern "C" void kernel_launch(void* const* d_in, const int* in_sizes, int n_in,
                              void* d_out, int out_size)
{
    // Input order per reference signature: mr (unused), pet, b, px, py, sx, sy
    const float* pet   = (const float*)d_in[1];
    const float* bfeat = (const float*)d_in[2];

    dim3 grid1(4, NG, NB);                   // 264 CTAs
    groupsum_kernel<<<grid1, 256>>>(pet, bfeat);

    dim3 grid2(17, 33, NB);                  // 1122 CTAs
    apply_kernel<<<grid2, 256>>>(bfeat, (float*)d_out);
}

// round 13
// speedup vs baseline: 1.3305x; 1.0809x over previous
#include <cuda_runtime.h>

#define HH 128
#define WW 128
#define CC 16
#define FF 16
#define CF (CC * FF)
#define NB 2
#define SNX 32
#define SNY 32
#define NG 33            // aligned 4x4 groups: start = 4g-2, g = 0..32

// Group sums: G = sum b over 4x4 group, P = sum pet*b. 1.1 MB each.
__device__ float g_G[(size_t)NB * NG * NG * CF];
__device__ float g_P[(size_t)NB * NG * NG * CF];

// 32-byte evict_last load (only legal width for the hint on this ptxas).
__device__ __forceinline__ void ldg_el32B(const float* p, float4& a, float4& b) {
    unsigned long long r0, r1, r2, r3;
    asm volatile("ld.global.nc.L2::evict_last.v4.b64 {%0,%1,%2,%3}, [%4];"
                 : "=l"(r0), "=l"(r1), "=l"(r2), "=l"(r3) : "l"(p));
    a.x = __uint_as_float((unsigned)r0); a.y = __uint_as_float((unsigned)(r0 >> 32));
    a.z = __uint_as_float((unsigned)r1); a.w = __uint_as_float((unsigned)(r1 >> 32));
    b.x = __uint_as_float((unsigned)r2); b.y = __uint_as_float((unsigned)(r2 >> 32));
    b.z = __uint_as_float((unsigned)r3); b.w = __uint_as_float((unsigned)(r3 >> 32));
}

// ---------------------------------------------------------------------------
// K1: group sums, double-buffered prefetch over groups (R11 version, ~4.4us).
// ---------------------------------------------------------------------------
__global__ __launch_bounds__(256) void groupsum_kernel(
    const float* __restrict__ pet, const float* __restrict__ bfeat)
{
    __shared__ float pet_s[4 * 36 * CC];   // 9.2 KB

    const int q  = blockIdx.x;             // 0..3
    const int gx = blockIdx.y;             // 0..32
    const int bz = blockIdx.z;
    const int t  = threadIdx.x;
    const int c  = t >> 4;

    const int ngy   = (q == 3) ? 9 : 8;
    const int gy0   = q * 8;
    const int c0    = 4 * gy0 - 2;
    const int ncols = 4 * ngy;
    const int r0    = 4 * gx - 2;

    for (int idx = t; idx < 4 * ncols * CC; idx += 256) {
        int cc = idx & 15, pix = idx >> 4;
        int u = pix / ncols, v = pix - u * ncols;
        int r = r0 + u, col = c0 + v;
        float val = 0.f;
        if ((unsigned)r < HH && (unsigned)col < WW)
            val = pet[((bz * HH + r) * WW + col) * CC + cc];
        pet_s[idx] = val;
    }
    __syncthreads();

    const float* bb = bfeat + (size_t)bz * HH * WW * CF + t;

    float buf[2][16];
    auto load_group = [&](int g, float* dst) {
#pragma unroll
        for (int u = 0; u < 4; u++) {
            int r = r0 + u;
            bool rowok = (unsigned)r < HH;
#pragma unroll
            for (int v = 0; v < 4; v++) {
                int col = c0 + 4 * g + v;
                float x = 0.f;
                if (rowok && (unsigned)col < WW)
                    x = __ldg(bb + (r * WW + col) * CF);
                dst[u * 4 + v] = x;
            }
        }
    };

    load_group(0, buf[0]);
#pragma unroll
    for (int g = 0; g < 9; g++) {
        if (g >= ngy) continue;
        if (g + 1 < ngy) load_group(g + 1, buf[(g + 1) & 1]);
        const float* B = buf[g & 1];
        float d = 0.f, p = 0.f;
#pragma unroll
        for (int u = 0; u < 4; u++)
#pragma unroll
            for (int v = 0; v < 4; v++) {
                float bv = B[u * 4 + v];
                float pv = pet_s[(u * ncols + 4 * g + v) * CC + c];
                d += bv;
                p = fmaf(pv, bv, p);
            }
        size_t o = (((size_t)bz * NG + gx) * NG + (gy0 + g)) * CF + t;
        g_G[o] = d;
        g_P[o] = p;
    }
}

// ---------------------------------------------------------------------------
// K2: out(x,y,c) = 0.25 * sum_f b * S.
// 32 threads/pixel, 32B evict_last loads, 4 y-pixels per thread.
// ---------------------------------------------------------------------------
template<bool FULL>
__device__ __forceinline__ void apply_impl(
    int A2, int a, int bz, int t,
    const float* __restrict__ bfeat, float* __restrict__ out)
{
    __shared__ float S2[2][CF];   // natural layout, index = cf

    const int q5 = t & 31;        // 32B slot within pixel record
    const int pp = t >> 5;        // warp id: i = pp&3 (x-row), yh = pp>>2
    const int i  = pp & 3;
    const int yh = pp >> 2;
    const int c  = q5 >> 1;       // channel this slot belongs to
    const int fh = q5 & 1;        // which 8-f half

    const int x = 4 * a - 2 + i;
    const bool okx = FULL || ((unsigned)x < HH);
    const float* rowbase = bfeat + ((size_t)(bz * HH + x) * WW) * CF + q5 * 8;
    const int y0 = 8 * A2 - 2 + 4 * yh;

    // ---- issue 4 independent 32B b loads first ----
    float4 bva[4], bvb[4];
#pragma unroll
    for (int m = 0; m < 4; m++) {
        int y = y0 + m;
        if (FULL || (okx && (unsigned)y < WW)) {
            ldg_el32B(rowbase + (size_t)y * CF, bva[m], bvb[m]);
        } else {
            bva[m] = make_float4(0.f, 0.f, 0.f, 0.f);
            bvb[m] = make_float4(0.f, 0.f, 0.f, 0.f);
        }
    }

    // ---- load G/P neighborhood folded into x-pair sums (t = cf index) ----
    float xg[2][4], xp[2][4];
#pragma unroll
    for (int j = 0; j < 4; j++) {
        int gy = 2 * A2 - 1 + j;
        float g0 = 0.f, g1 = 0.f, g2v = 0.f;
        float p0 = 0.f, p1 = 0.f, p2v = 0.f;
        if (FULL || (unsigned)gy < NG) {
#pragma unroll
            for (int ii = 0; ii < 3; ii++) {
                int gxx = a - 1 + ii;
                if (!FULL && (unsigned)gxx >= NG) continue;
                size_t o = (((size_t)bz * NG + gxx) * NG + gy) * CF + t;
                float gv = __ldg(&g_G[o]);
                float pv = __ldg(&g_P[o]);
                if (ii == 0)      { g0 = gv; p0 = pv; }
                else if (ii == 1) { g1 = gv; p1 = pv; }
                else              { g2v = gv; p2v = pv; }
            }
        }
        xg[0][j] = g0 + g1;  xg[1][j] = g1 + g2v;
        xp[0][j] = p0 + p1;  xp[1][j] = p1 + p2v;
    }

    // ---- S for the two y-blocks ----
#pragma unroll
    for (int s = 0; s < 2; s++) {
        int blk = 2 * A2 + s;
        float acc = 0.f;
#pragma unroll
        for (int da = 0; da < 2; da++) {
            int snx = a - 1 + da;
            if (!FULL && (unsigned)snx >= SNX) continue;
#pragma unroll
            for (int db = 0; db < 2; db++) {
                int sny = blk - 1 + db;
                if (!FULL && (unsigned)sny >= SNY) continue;
                int j0 = s + db;
                float g2 = xg[da][j0] + xg[da][j0 + 1];
                float p2 = xp[da][j0] + xp[da][j0 + 1];
                acc += (g2 != 0.f) ? (p2 / g2) : 0.f;   // divide_no_nan
            }
        }
        S2[s][t] = acc;
    }
    __syncthreads();

    // thread's 8 S values are contiguous at cf = q5*8 (s block = yh half)
    const int s = yh >> 1;        // yh 0,1 -> block 0; yh 2,3 -> block 1... no:
    // y-blocks: block 0 covers y0 range m<4 when yh==0 or 1? y = 8*A2-2+4*yh+m.
    // block s covers y in [8*A2-2+4s, 8*A2+2+4s): exactly yh == s. So s = yh... 
    // yh in 0..1 only when pp>>2 in 0..1 — pp goes 0..7 so yh in 0..1. s = yh.
    const float4 sv0 = *(const float4*)(&S2[yh][q5 * 8]);
    const float4 sv1 = *(const float4*)(&S2[yh][q5 * 8 + 4]);

    const bool lead = (fh == 0);
#pragma unroll
    for (int m = 0; m < 4; m++) {
        int y = y0 + m;
        float dot = bva[m].x * sv0.x + bva[m].y * sv0.y
                  + bva[m].z * sv0.z + bva[m].w * sv0.w
                  + bvb[m].x * sv1.x + bvb[m].y * sv1.y
                  + bvb[m].z * sv1.z + bvb[m].w * sv1.w;
        dot += __shfl_xor_sync(0xffffffffu, dot, 1);
        if (lead && (FULL || (okx && (unsigned)y < WW)))
            out[((bz * HH + x) * WW + y) * CC + c] = 0.25f * dot;
    }
}

__global__ __launch_bounds__(256) void apply_kernel(
    const float* __restrict__ bfeat, float* __restrict__ out)
{
    const int A2 = blockIdx.x;   // 0..16
    const int a  = blockIdx.y;   // 0..32
    const int bz = blockIdx.z;
    const int t  = threadIdx.x;

    const bool interior = (a >= 1) && (a <= 31) && (A2 >= 1) && (A2 <= 15);
    if (interior) apply_impl<true >(A2, a, bz, t, bfeat, out);
    else          apply_impl<false>(A2, a, bz, t, bfeat, out);
}

extern "C" void kernel_launch(void* const* d_in, const int* in_sizes, int n_in,
                              void* d_out, int out_size)
{
    // Input order per reference signature: mr (unused), pet, b, px, py, sx, sy
    const float* pet   = (const float*)d_in[1];
    const float* bfeat = (const float*)d_in[2];

    dim3 grid1(4, NG, NB);                   // 264 CTAs
    groupsum_kernel<<<grid1, 256>>>(pet, bfeat);

    dim3 grid2(17, 33, NB);                  // 1122 CTAs
    apply_kernel<<<grid2, 256>>>(bfeat, (float*)d_out);
}

// round 14
// speedup vs baseline: 1.3557x; 1.0189x over previous
#include <cuda_runtime.h>

#define HH 128
#define WW 128
#define CC 16
#define FF 16
#define CF (CC * FF)
#define NB 2
#define SNX 32
#define SNY 32
#define NG 33            // aligned 4x4 groups: start = 4g-2, g = 0..32

// Group sums: G = sum b over 4x4 group, P = sum pet*b. 1.1 MB each.
__device__ float g_G[(size_t)NB * NG * NG * CF];
__device__ float g_P[(size_t)NB * NG * NG * CF];

// 32-byte evict_last load (only legal width for the hint on this ptxas).
__device__ __forceinline__ void ldg_el32B(const float* p, float4& a, float4& b) {
    unsigned long long r0, r1, r2, r3;
    asm volatile("ld.global.nc.L2::evict_last.v4.b64 {%0,%1,%2,%3}, [%4];"
                 : "=l"(r0), "=l"(r1), "=l"(r2), "=l"(r3) : "l"(p));
    a.x = __uint_as_float((unsigned)r0); a.y = __uint_as_float((unsigned)(r0 >> 32));
    a.z = __uint_as_float((unsigned)r1); a.w = __uint_as_float((unsigned)(r1 >> 32));
    b.x = __uint_as_float((unsigned)r2); b.y = __uint_as_float((unsigned)(r2 >> 32));
    b.z = __uint_as_float((unsigned)r3); b.w = __uint_as_float((unsigned)(r3 >> 32));
}

// ---------------------------------------------------------------------------
// K1: group sums, double-buffered prefetch over groups (proven ~4.4us).
// ---------------------------------------------------------------------------
__global__ __launch_bounds__(256) void groupsum_kernel(
    const float* __restrict__ pet, const float* __restrict__ bfeat)
{
    __shared__ float pet_s[4 * 36 * CC];   // 9.2 KB

    const int q  = blockIdx.x;             // 0..3
    const int gx = blockIdx.y;             // 0..32
    const int bz = blockIdx.z;
    const int t  = threadIdx.x;
    const int c  = t >> 4;

    const int ngy   = (q == 3) ? 9 : 8;
    const int gy0   = q * 8;
    const int c0    = 4 * gy0 - 2;
    const int ncols = 4 * ngy;
    const int r0    = 4 * gx - 2;

    for (int idx = t; idx < 4 * ncols * CC; idx += 256) {
        int cc = idx & 15, pix = idx >> 4;
        int u = pix / ncols, v = pix - u * ncols;
        int r = r0 + u, col = c0 + v;
        float val = 0.f;
        if ((unsigned)r < HH && (unsigned)col < WW)
            val = pet[((bz * HH + r) * WW + col) * CC + cc];
        pet_s[idx] = val;
    }
    __syncthreads();

    const float* bb = bfeat + (size_t)bz * HH * WW * CF + t;

    float buf[2][16];
    auto load_group = [&](int g, float* dst) {
#pragma unroll
        for (int u = 0; u < 4; u++) {
            int r = r0 + u;
            bool rowok = (unsigned)r < HH;
#pragma unroll
            for (int v = 0; v < 4; v++) {
                int col = c0 + 4 * g + v;
                float x = 0.f;
                if (rowok && (unsigned)col < WW)
                    x = __ldg(bb + (r * WW + col) * CF);
                dst[u * 4 + v] = x;
            }
        }
    };

    load_group(0, buf[0]);
#pragma unroll
    for (int g = 0; g < 9; g++) {
        if (g >= ngy) continue;
        if (g + 1 < ngy) load_group(g + 1, buf[(g + 1) & 1]);
        const float* B = buf[g & 1];
        float d = 0.f, p = 0.f;
#pragma unroll
        for (int u = 0; u < 4; u++)
#pragma unroll
            for (int v = 0; v < 4; v++) {
                float bv = B[u * 4 + v];
                float pv = pet_s[(u * ncols + 4 * g + v) * CC + c];
                d += bv;
                p = fmaf(pv, bv, p);
            }
        size_t o = (((size_t)bz * NG + gx) * NG + (gy0 + g)) * CF + t;
        g_G[o] = d;
        g_P[o] = p;
    }
}

// ---------------------------------------------------------------------------
// K2: out(x,y,c) = 0.25 * sum_f b * S.
// CTA = 4 x-rows x 16 y (4 y-blocks). Warp = 1 x-row, 8 y-pixels (2m + parity),
// each load = contiguous 1KB warp transaction, prefetch distance 2.
// ---------------------------------------------------------------------------
template<bool FULL>
__device__ __forceinline__ void apply_impl(
    int qy, int a, int bz, int t,
    const float* __restrict__ bfeat, float* __restrict__ out)
{
    __shared__ float S2[4][CF];   // [y-block][cf]

    const int q5 = t & 31;        // 32B slot within pixel record
    const int pp = t >> 5;        // warp id
    const int i  = pp & 3;        // x-row
    const int jh = pp >> 2;       // y parity (0/1)
    const int c  = q5 >> 1;
    const int fh = q5 & 1;

    const int x = 4 * a - 2 + i;
    const bool okx = FULL || ((unsigned)x < HH);
    const float* rowbase = bfeat + ((size_t)(bz * HH + x) * WW) * CF + q5 * 8;
    const int y0 = 16 * qy - 2 + jh;     // warp's y sequence: y0 + 2m, m=0..7

    float4 bufA[3], bufB[3];
    auto load_m = [&](int m) {
        int y = y0 + 2 * m;
        int slot = m % 3;
        if (FULL || (okx && (unsigned)y < WW)) {
            ldg_el32B(rowbase + (size_t)y * CF, bufA[slot], bufB[slot]);
        } else {
            bufA[slot] = make_float4(0.f, 0.f, 0.f, 0.f);
            bufB[slot] = make_float4(0.f, 0.f, 0.f, 0.f);
        }
    };
    load_m(0);
    load_m(1);

    // ---- stream 6 G/P rows (gy = 4qy-1..4qy+4), build S[0..3] ----
    {
        float S[4] = {0.f, 0.f, 0.f, 0.f};
        float xg0p = 0.f, xg1p = 0.f, xp0p = 0.f, xp1p = 0.f;
#pragma unroll
        for (int w = 0; w <= 5; w++) {
            int gy = 4 * qy - 1 + w;
            float g0 = 0.f, g1 = 0.f, g2v = 0.f;
            float p0 = 0.f, p1 = 0.f, p2v = 0.f;
            if (FULL || (unsigned)gy < NG) {
#pragma unroll
                for (int ii = 0; ii < 3; ii++) {
                    int gxx = a - 1 + ii;
                    if (!FULL && (unsigned)gxx >= NG) continue;
                    size_t o = (((size_t)bz * NG + gxx) * NG + gy) * CF + t;
                    float gv = __ldg(&g_G[o]);
                    float pv = __ldg(&g_P[o]);
                    if (ii == 0)      { g0 = gv; p0 = pv; }
                    else if (ii == 1) { g1 = gv; p1 = pv; }
                    else              { g2v = gv; p2v = pv; }
                }
            }
            float xg0 = g0 + g1, xg1 = g1 + g2v;
            float xp0 = p0 + p1, xp1 = p1 + p2v;
            if (w >= 1) {
                int sny = 4 * qy - 2 + w;
                float rsum = 0.f;
                if (FULL || (unsigned)sny < SNY) {
                    float G20 = xg0p + xg0, P20 = xp0p + xp0;
                    float G21 = xg1p + xg1, P21 = xp1p + xp1;
                    if ((FULL || (unsigned)(a - 1) < SNX) && G20 != 0.f) rsum += P20 / G20;
                    if ((FULL || (unsigned)a < SNX)       && G21 != 0.f) rsum += P21 / G21;
                }
                int s1 = w - 2;               // window sny covers blocks s1, s1+1
                if (s1 >= 0)     S[s1] += rsum;
                if (s1 + 1 <= 3) S[s1 + 1] += rsum;
            }
            xg0p = xg0; xg1p = xg1; xp0p = xp0; xp1p = xp1;
        }
#pragma unroll
        for (int s = 0; s < 4; s++) S2[s][t] = S[s];
    }
    __syncthreads();

    // ---- pipelined apply over 8 y-pixels per warp ----
    const bool lead = (fh == 0);
#pragma unroll
    for (int m = 0; m < 8; m++) {
        if (m + 2 < 8) load_m(m + 2);
        const int slot = m % 3;
        const int jy = 2 * m + jh;
        const int s  = jy >> 2;
        const float4 sv0 = *(const float4*)(&S2[s][q5 * 8]);
        const float4 sv1 = *(const float4*)(&S2[s][q5 * 8 + 4]);
        const float4 ba = bufA[slot], bb = bufB[slot];
        float dot = ba.x * sv0.x + ba.y * sv0.y + ba.z * sv0.z + ba.w * sv0.w
                  + bb.x * sv1.x + bb.y * sv1.y + bb.z * sv1.z + bb.w * sv1.w;
        dot += __shfl_xor_sync(0xffffffffu, dot, 1);
        const int y = y0 + 2 * m;
        if (lead && (FULL || (okx && (unsigned)y < WW)))
            out[((bz * HH + x) * WW + y) * CC + c] = 0.25f * dot;
    }
}

__global__ __launch_bounds__(256) void apply_kernel(
    const float* __restrict__ bfeat, float* __restrict__ out)
{
    const int qy = blockIdx.x;   // 0..8 (y quarter of 16)
    const int a  = blockIdx.y;   // 0..32
    const int bz = blockIdx.z;
    const int t  = threadIdx.x;

    const bool interior = (a >= 1) && (a <= 31) && (qy >= 1) && (qy <= 7);
    if (interior) apply_impl<true >(qy, a, bz, t, bfeat, out);
    else          apply_impl<false>(qy, a, bz, t, bfeat, out);
}

extern "C" void kernel_launch(void* const* d_in, const int* in_sizes, int n_in,
                              void* d_out, int out_size)
{
    // Input order per reference signature: mr (unused), pet, b, px, py, sx, sy
    const float* pet   = (const float*)d_in[1];
    const float* bfeat = (const float*)d_in[2];

    dim3 grid1(4, NG, NB);                   // 264 CTAs
    groupsum_kernel<<<grid1, 256>>>(pet, bfeat);

    dim3 grid2(9, NG, NB);                   // 594 CTAs
    apply_kernel<<<grid2, 256>>>(bfeat, (float*)d_out);
}